// round 4
// baseline (speedup 1.0000x reference)
#include <cuda_runtime.h>
#include <math.h>

// Problem constants
#define B_  128
#define T_  512
#define I_  300
#define H_  256
#define G4_ 1024  // 4*H

typedef unsigned long long ull;

// ---------------- scratch (device globals; no allocation allowed) ----------
__device__ float g_xp[(size_t)B_ * T_ * G4_];   // forward input projections (256 MB)
__device__ float g_xpb[B_ * G4_];               // backward proj at t = T-1
__device__ float g_hst[2 * B_ * H_];            // ping-pong h buffers
__device__ float g_hb[B_ * H_];                 // backward final h
__device__ unsigned int g_count;                // grid barrier counter

// ---------------- f32x2 helpers -------------------------------------------
__device__ __forceinline__ void fma2(ull& d, ull a, ull b) {
    asm("fma.rn.f32x2 %0, %1, %2, %0;" : "+l"(d) : "l"(a), "l"(b));
}
__device__ __forceinline__ ull dup2(float a) {
    ull r; asm("mov.b64 %0, {%1, %1};" : "=l"(r) : "f"(a)); return r;
}
__device__ __forceinline__ float2 unpk(ull v) {
    float2 f; asm("mov.b64 {%0, %1}, %2;" : "=f"(f.x), "=f"(f.y) : "l"(v)); return f;
}
__device__ __forceinline__ float sigf(float x) { return 1.0f / (1.0f + __expf(-x)); }

// ---------------- init: zero h buffer 0 + barrier counter ------------------
__global__ void init_k() {
    int i = blockIdx.x * blockDim.x + threadIdx.x;
    if (i < B_ * H_) g_hst[i] = 0.0f;
    if (i == 0) g_count = 0u;
}

// ---------------- SGEMM: C[M,N] = A[M,K] * B[N,K]^T + bias[N] --------------
// BM=BN=128, BK=8, 256 threads, 8x8 per thread, packed f32x2 math.
// Grid must exactly tile M,N (M%128==0, N%128==0). K arbitrary (guarded, K%4==0).
__global__ __launch_bounds__(256, 2) void sgemm_tn(
    const float* __restrict__ A, int lda,
    const float* __restrict__ Bm,  // ldb = K
    const float* __restrict__ bias,
    float* __restrict__ C, int ldc, int K)
{
    __shared__ float As[8][128];
    __shared__ float Bs[8][128];

    int tid = threadIdx.x;
    int tx = tid & 15, ty = tid >> 4;
    long mBase = (long)blockIdx.y * 128;
    int  nBase = blockIdx.x * 128;

    int lr = tid >> 1;         // 0..127 (row within tile)
    int lc = (tid & 1) * 4;    // 0 or 4 (k sub-col)
    const float* Aptr = A + (mBase + lr) * (long)lda;
    const float* Bptr = Bm + (long)(nBase + lr) * K;

    ull acc[8][4];
#pragma unroll
    for (int i = 0; i < 8; ++i)
#pragma unroll
        for (int j = 0; j < 4; ++j) acc[i][j] = 0ull;

    int ktiles = (K + 7) / 8;
    for (int kt = 0; kt < ktiles; ++kt) {
        int k0 = kt * 8;
        float4 av = make_float4(0.f, 0.f, 0.f, 0.f);
        float4 bv = make_float4(0.f, 0.f, 0.f, 0.f);
        if (k0 + lc < K) av = *reinterpret_cast<const float4*>(Aptr + k0 + lc);
        if (k0 + lc < K) bv = *reinterpret_cast<const float4*>(Bptr + k0 + lc);
        __syncthreads();
        As[lc + 0][lr] = av.x; As[lc + 1][lr] = av.y;
        As[lc + 2][lr] = av.z; As[lc + 3][lr] = av.w;
        Bs[lc + 0][lr] = bv.x; Bs[lc + 1][lr] = bv.y;
        Bs[lc + 2][lr] = bv.z; Bs[lc + 3][lr] = bv.w;
        __syncthreads();

#pragma unroll
        for (int kk = 0; kk < 8; ++kk) {
            float4 a0 = *reinterpret_cast<const float4*>(&As[kk][ty * 4]);
            float4 a1 = *reinterpret_cast<const float4*>(&As[kk][64 + ty * 4]);
            ulonglong2 b0 = *reinterpret_cast<const ulonglong2*>(&Bs[kk][tx * 4]);
            ulonglong2 b1 = *reinterpret_cast<const ulonglong2*>(&Bs[kk][64 + tx * 4]);
            float aa[8] = {a0.x, a0.y, a0.z, a0.w, a1.x, a1.y, a1.z, a1.w};
            ull bb[4] = {b0.x, b0.y, b1.x, b1.y};
#pragma unroll
            for (int i = 0; i < 8; ++i) {
                ull ad = dup2(aa[i]);
#pragma unroll
                for (int j = 0; j < 4; ++j) fma2(acc[i][j], ad, bb[j]);
            }
        }
    }

    float4 bias0 = *reinterpret_cast<const float4*>(&bias[nBase + tx * 4]);
    float4 bias1 = *reinterpret_cast<const float4*>(&bias[nBase + 64 + tx * 4]);
#pragma unroll
    for (int i = 0; i < 8; ++i) {
        long m = mBase + ((i < 4) ? (ty * 4 + i) : (64 + ty * 4 + (i - 4)));
        float2 c0 = unpk(acc[i][0]);
        float2 c1 = unpk(acc[i][1]);
        float2 c2 = unpk(acc[i][2]);
        float2 c3 = unpk(acc[i][3]);
        float4 o0 = make_float4(c0.x + bias0.x, c0.y + bias0.y, c1.x + bias0.z, c1.y + bias0.w);
        float4 o1 = make_float4(c2.x + bias1.x, c2.y + bias1.y, c3.x + bias1.z, c3.y + bias1.w);
        *reinterpret_cast<float4*>(&C[m * ldc + nBase + tx * 4]) = o0;
        *reinterpret_cast<float4*>(&C[m * ldc + nBase + 64 + tx * 4]) = o1;
    }
}

// ---------------- backward direction: single LSTM step from zero state -----
__global__ void bstep_k() {
    int idx = blockIdx.x * 256 + threadIdx.x;   // 128 blocks * 256 = 32768
    int b = idx >> 8, h = idx & 255;
    const float* r = g_xpb + (size_t)b * G4_;
    float ig = sigf(r[h]);
    float gg = tanhf(r[512 + h]);
    float og = sigf(r[768 + h]);
    float c = ig * gg;                  // f*0 + i*g
    g_hb[idx] = og * tanhf(c);
}

// ---------------- persistent forward recurrence ----------------------------
// 128 CTAs x 256 threads. CTA = (btile 0..3)*(htile 0..31).
// Thread = (kh 0..1, hcol 0..7, bpair 0..15). Accumulate 2 batches via f32x2.
// W_hh tile duplicated into smem ONCE (64 KB). c lives in registers.
#define SMEM_WD   65536                 // 8*4*256 float2
#define SMEM_HS   33024                 // 16*258 float2 (padded)
#define SMEM_RED  4096                  // 128*4 ull
#define SMEM_TOT  (SMEM_WD + SMEM_HS + SMEM_RED)

__global__ __launch_bounds__(256, 1) void lstm_fwd(const float* __restrict__ Whh)
{
    extern __shared__ char smem[];
    float2* Wd = reinterpret_cast<float2*>(smem);
    float2* Hs = reinterpret_cast<float2*>(smem + SMEM_WD);
    float*  Hsf = reinterpret_cast<float*>(Hs);
    ull*   Red = reinterpret_cast<ull*>(smem + SMEM_WD + SMEM_HS);

    int tid = threadIdx.x;
    int kh = tid >> 7;           // k half
    int r  = tid & 127;
    int hcol = r >> 4;           // 0..7
    int bp   = r & 15;           // 0..15
    int cta = blockIdx.x;
    int btile = cta & 3;
    int htile = cta >> 2;
    int b0  = btile * 32 + bp * 2;
    int hcg = htile * 8 + hcol;

    // load W_hh rows for this CTA's 8 h-cols x 4 gates, duplicated into f32x2
    for (int idx = tid; idx < 8 * 4 * 256; idx += 256) {
        int hl  = idx >> 10;
        int rem = idx & 1023;
        int gt  = rem >> 8;
        int k   = rem & 255;
        float w = Whh[(size_t)(gt * 256 + htile * 8 + hl) * 256 + k];
        Wd[idx] = make_float2(w, w);
    }

    float c0 = 0.0f, c1 = 0.0f;
    int row = tid >> 3;                  // 0..31 (h row to stage)
    int kb  = (tid & 7) * 4;
    int hs_row = row >> 1, comp = row & 1;

    for (int t = 0; t < T_; ++t) {
        const float* hread  = g_hst + (t & 1) * (B_ * H_);
        float*       hwrite = g_hst + ((t + 1) & 1) * (B_ * H_);

        // stage h tile (32 batches x 256) into smem as batch-pairs, via L2
        {
            const float* src = hread + (size_t)(btile * 32 + row) * 256;
#pragma unroll
            for (int i = 0; i < 8; ++i) {
                int k = kb + i * 32;
                float4 v = __ldcg(reinterpret_cast<const float4*>(src + k));
                float* d = Hsf + ((size_t)hs_row * 258 + k) * 2 + comp;
                d[0] = v.x; d[2] = v.y; d[4] = v.z; d[6] = v.w;
            }
        }
        // prefetch xp for this step (kh==0 threads do the epilogue)
        float xi0=0.f, xf0=0.f, xg0=0.f, xo0=0.f, xi1=0.f, xf1=0.f, xg1=0.f, xo1=0.f;
        if (kh == 0) {
            const float* xp0 = g_xp + (((size_t)b0 * T_ + t) << 10) + hcg;
            const float* xp1 = xp0 + (size_t)T_ * G4_;
            xi0 = xp0[0]; xf0 = xp0[256]; xg0 = xp0[512]; xo0 = xp0[768];
            xi1 = xp1[0]; xf1 = xp1[256]; xg1 = xp1[512]; xo1 = xp1[768];
        }
        __syncthreads();

        // k loop: 128 k per thread, 2 k per iteration, f32x2 over batch pair
        ull a_i = 0ull, a_f = 0ull, a_g = 0ull, a_o = 0ull;
        const ulonglong2* hp = reinterpret_cast<const ulonglong2*>(Hs + bp * 258 + kh * 128);
        const ulonglong2* w0 = reinterpret_cast<const ulonglong2*>(Wd + (hcol * 4 + 0) * 256 + kh * 128);
        const ulonglong2* w1 = reinterpret_cast<const ulonglong2*>(Wd + (hcol * 4 + 1) * 256 + kh * 128);
        const ulonglong2* w2 = reinterpret_cast<const ulonglong2*>(Wd + (hcol * 4 + 2) * 256 + kh * 128);
        const ulonglong2* w3 = reinterpret_cast<const ulonglong2*>(Wd + (hcol * 4 + 3) * 256 + kh * 128);
#pragma unroll 16
        for (int it = 0; it < 64; ++it) {
            ulonglong2 hv = hp[it];
            ulonglong2 wa = w0[it]; fma2(a_i, hv.x, wa.x); fma2(a_i, hv.y, wa.y);
            ulonglong2 wb = w1[it]; fma2(a_f, hv.x, wb.x); fma2(a_f, hv.y, wb.y);
            ulonglong2 wc = w2[it]; fma2(a_g, hv.x, wc.x); fma2(a_g, hv.y, wc.y);
            ulonglong2 wd = w3[it]; fma2(a_o, hv.x, wd.x); fma2(a_o, hv.y, wd.y);
        }

        // combine k halves
        if (kh == 1) {
            ull* rp = Red + (size_t)r * 4;
            rp[0] = a_i; rp[1] = a_f; rp[2] = a_g; rp[3] = a_o;
        }
        __syncthreads();
        if (kh == 0) {
            ull* rp = Red + (size_t)r * 4;
            float2 si = unpk(a_i), sf = unpk(a_f), sg = unpk(a_g), so = unpk(a_o);
            float2 q;
            q = unpk(rp[0]); si.x += q.x; si.y += q.y;
            q = unpk(rp[1]); sf.x += q.x; sf.y += q.y;
            q = unpk(rp[2]); sg.x += q.x; sg.y += q.y;
            q = unpk(rp[3]); so.x += q.x; so.y += q.y;

            float I0 = sigf(si.x + xi0), F0 = sigf(sf.x + xf0);
            float G0 = tanhf(sg.x + xg0), O0 = sigf(so.x + xo0);
            c0 = F0 * c0 + I0 * G0;
            float h0v = O0 * tanhf(c0);

            float I1 = sigf(si.y + xi1), F1 = sigf(sf.y + xf1);
            float G1 = tanhf(sg.y + xg1), O1 = sigf(so.y + xo1);
            c1 = F1 * c1 + I1 * G1;
            float h1v = O1 * tanhf(c1);

            hwrite[(size_t)b0 * 256 + hcg]       = h0v;
            hwrite[(size_t)(b0 + 1) * 256 + hcg] = h1v;
        }

        if (t != T_ - 1) {
            __threadfence();
            __syncthreads();
            if (tid == 0) {
                atomicAdd(&g_count, 1u);
                unsigned tgt = (unsigned)(t + 1) * gridDim.x;
                while (*((volatile unsigned int*)&g_count) < tgt) { }
            }
            __syncthreads();
        }
    }
}

// ---------------- final linear: out = [hf, hb] @ W_lin^T + b_lin -----------
__global__ void final_k(const float* __restrict__ Wl, const float* __restrict__ bl,
                        float* __restrict__ out)
{
    __shared__ float s0[8], s1[8];
    int b = blockIdx.x, h = threadIdx.x;   // 256 threads
    float hf = g_hst[(size_t)b * 256 + h];            // final h is in buffer 0
    float hb = g_hb[(size_t)b * 256 + h];
    float p0 = hf * Wl[h]       + hb * Wl[256 + h];
    float p1 = hf * Wl[512 + h] + hb * Wl[768 + h];
#pragma unroll
    for (int o = 16; o; o >>= 1) {
        p0 += __shfl_down_sync(0xffffffffu, p0, o);
        p1 += __shfl_down_sync(0xffffffffu, p1, o);
    }
    if ((h & 31) == 0) { s0[h >> 5] = p0; s1[h >> 5] = p1; }
    __syncthreads();
    if (h == 0) {
        float a = 0.f, c = 0.f;
#pragma unroll
        for (int i = 0; i < 8; ++i) { a += s0[i]; c += s1[i]; }
        out[b * 2 + 0] = a + bl[0];
        out[b * 2 + 1] = c + bl[1];
    }
}

// ---------------- host entry ----------------------------------------------
extern "C" void kernel_launch(void* const* d_in, const int* in_sizes, int n_in,
                              void* d_out, int out_size)
{
    const float* x    = (const float*)d_in[0];
    const float* Wihf = (const float*)d_in[1];
    const float* Whhf = (const float*)d_in[2];
    const float* bf   = (const float*)d_in[3];
    const float* Wihb = (const float*)d_in[4];
    const float* bb   = (const float*)d_in[6];
    const float* Wl   = (const float*)d_in[7];
    const float* bl   = (const float*)d_in[8];
    float* out = (float*)d_out;

    void *xp_p = nullptr, *xpb_p = nullptr;
    cudaGetSymbolAddress(&xp_p, g_xp);
    cudaGetSymbolAddress(&xpb_p, g_xpb);

    static bool attr_set = false;
    if (!attr_set) {
        cudaFuncSetAttribute(lstm_fwd, cudaFuncAttributeMaxDynamicSharedMemorySize, SMEM_TOT);
        attr_set = true;
    }

    // 1) zero h buffer 0 + barrier counter
    init_k<<<128, 256>>>();
    // 2) xp_f = x @ W_ih_f^T + b_f   (M=65536, N=1024, K=300)
    sgemm_tn<<<dim3(8, 512), 256>>>(x, I_, Wihf, bf, (float*)xp_p, G4_, I_);
    // 3) xp_b at t = T-1 only        (M=128, N=1024, K=300)
    sgemm_tn<<<dim3(8, 1), 256>>>(x + (size_t)(T_ - 1) * I_, T_ * I_, Wihb, bb,
                                  (float*)xpb_p, G4_, I_);
    // 4) backward direction = one LSTM step
    bstep_k<<<128, 256>>>();
    // 5) forward recurrence (persistent, 512 steps)
    lstm_fwd<<<128, 256, SMEM_TOT>>>(Whhf);
    // 6) final linear
    final_k<<<128, 256>>>(Wl, bl, out);
}

// round 6
// speedup vs baseline: 1.3612x; 1.3612x over previous
#include <cuda_runtime.h>
#include <math.h>

// Problem constants
#define B_  128
#define T_  512
#define I_  300
#define H_  256
#define G4_ 1024  // 4*H

typedef unsigned long long ull;

// ---------------- scratch (device globals; no allocation allowed) ----------
__device__ float g_xp[(size_t)T_ * G4_ * B_];   // forward projections, [t][g][b] (256 MB)
__device__ float g_xpb[B_ * G4_];               // backward proj at t = T-1, [b][g]
__device__ float g_hst[2 * B_ * H_];            // ping-pong h buffers
__device__ float g_hb[B_ * H_];                 // backward final h
__device__ unsigned int g_flags[128];           // per-CTA step flags [btile*32 + htile]

// ---------------- f32x2 helpers -------------------------------------------
__device__ __forceinline__ void fma2(ull& d, ull a, ull b) {
    asm("fma.rn.f32x2 %0, %1, %2, %0;" : "+l"(d) : "l"(a), "l"(b));
}
__device__ __forceinline__ ull dup2(float a) {
    ull r; asm("mov.b64 %0, {%1, %1};" : "=l"(r) : "f"(a)); return r;
}
__device__ __forceinline__ float2 unpk(ull v) {
    float2 f; asm("mov.b64 {%0, %1}, %2;" : "=f"(f.x), "=f"(f.y) : "l"(v)); return f;
}
__device__ __forceinline__ float sigf(float x) { return 1.0f / (1.0f + __expf(-x)); }

// ---------------- init: zero h buffer 0 + flags (every replay) -------------
__global__ void init_k() {
    int i = blockIdx.x * blockDim.x + threadIdx.x;
    if (i < B_ * H_) g_hst[i] = 0.0f;
    if (i < 128) g_flags[i] = 0u;
}

// ---------------- SGEMM: C = A[M,K] * B[N,K]^T + bias[N] -------------------
// BM=BN=128, BK=8, 256 threads, 8x8 per thread, packed f32x2 math.
// mode 0: C row-major [M, G4_].  mode 1: scatter to [t][n][b] with m = b*512+t.
__global__ __launch_bounds__(256, 2) void sgemm_tn(
    const float* __restrict__ A, int lda,
    const float* __restrict__ Bm,  // ldb = K
    const float* __restrict__ bias,
    float* __restrict__ C, int K, int mode)
{
    __shared__ float As[8][128];
    __shared__ float Bs[8][128];

    int tid = threadIdx.x;
    int tx = tid & 15, ty = tid >> 4;
    int mBase = blockIdx.y * 128;
    int nBase = blockIdx.x * 128;

    int lr = tid >> 1;         // 0..127 (row within tile)
    int lc = (tid & 1) * 4;    // 0 or 4 (k sub-col)
    const float* Aptr = A + (size_t)(mBase + lr) * lda;
    const float* Bptr = Bm + (size_t)(nBase + lr) * K;

    ull acc[8][4];
#pragma unroll
    for (int i = 0; i < 8; ++i)
#pragma unroll
        for (int j = 0; j < 4; ++j) acc[i][j] = 0ull;

    int ktiles = (K + 7) / 8;
    for (int kt = 0; kt < ktiles; ++kt) {
        int k0 = kt * 8;
        float4 av = make_float4(0.f, 0.f, 0.f, 0.f);
        float4 bv = make_float4(0.f, 0.f, 0.f, 0.f);
        if (k0 + lc < K) av = *reinterpret_cast<const float4*>(Aptr + k0 + lc);
        if (k0 + lc < K) bv = *reinterpret_cast<const float4*>(Bptr + k0 + lc);
        __syncthreads();
        As[lc + 0][lr] = av.x; As[lc + 1][lr] = av.y;
        As[lc + 2][lr] = av.z; As[lc + 3][lr] = av.w;
        Bs[lc + 0][lr] = bv.x; Bs[lc + 1][lr] = bv.y;
        Bs[lc + 2][lr] = bv.z; Bs[lc + 3][lr] = bv.w;
        __syncthreads();

#pragma unroll
        for (int kk = 0; kk < 8; ++kk) {
            float4 a0 = *reinterpret_cast<const float4*>(&As[kk][ty * 4]);
            float4 a1 = *reinterpret_cast<const float4*>(&As[kk][64 + ty * 4]);
            ulonglong2 b0 = *reinterpret_cast<const ulonglong2*>(&Bs[kk][tx * 4]);
            ulonglong2 b1 = *reinterpret_cast<const ulonglong2*>(&Bs[kk][64 + tx * 4]);
            float aa[8] = {a0.x, a0.y, a0.z, a0.w, a1.x, a1.y, a1.z, a1.w};
            ull bb[4] = {b0.x, b0.y, b1.x, b1.y};
#pragma unroll
            for (int i = 0; i < 8; ++i) {
                ull ad = dup2(aa[i]);
#pragma unroll
                for (int j = 0; j < 4; ++j) fma2(acc[i][j], ad, bb[j]);
            }
        }
    }

    float4 bias0 = *reinterpret_cast<const float4*>(&bias[nBase + tx * 4]);
    float4 bias1 = *reinterpret_cast<const float4*>(&bias[nBase + 64 + tx * 4]);
#pragma unroll
    for (int i = 0; i < 8; ++i) {
        int m = mBase + ((i < 4) ? (ty * 4 + i) : (64 + ty * 4 + (i - 4)));
        float2 c0 = unpk(acc[i][0]);
        float2 c1 = unpk(acc[i][1]);
        float2 c2 = unpk(acc[i][2]);
        float2 c3 = unpk(acc[i][3]);
        float v0[4] = {c0.x + bias0.x, c0.y + bias0.y, c1.x + bias0.z, c1.y + bias0.w};
        float v1[4] = {c2.x + bias1.x, c2.y + bias1.y, c3.x + bias1.z, c3.y + bias1.w};
        if (mode == 0) {
            float* p = C + (size_t)m * G4_ + nBase;
            *reinterpret_cast<float4*>(p + tx * 4)      = make_float4(v0[0], v0[1], v0[2], v0[3]);
            *reinterpret_cast<float4*>(p + 64 + tx * 4) = make_float4(v1[0], v1[1], v1[2], v1[3]);
        } else {
            int b = m >> 9, t = m & 511;
            size_t base = ((size_t)t * G4_) * B_ + b;
            int n0 = nBase + tx * 4;
            int n1 = nBase + 64 + tx * 4;
#pragma unroll
            for (int j = 0; j < 4; ++j) C[base + (size_t)(n0 + j) * B_] = v0[j];
#pragma unroll
            for (int j = 0; j < 4; ++j) C[base + (size_t)(n1 + j) * B_] = v1[j];
        }
    }
}

// ---------------- backward direction: single LSTM step from zero state -----
__global__ void bstep_k() {
    int idx = blockIdx.x * 256 + threadIdx.x;
    int b = idx >> 8, h = idx & 255;
    const float* r = g_xpb + (size_t)b * G4_;
    float ig = sigf(r[h]);
    float gg = tanhf(r[512 + h]);
    float og = sigf(r[768 + h]);
    float c = ig * gg;
    g_hb[idx] = og * tanhf(c);
}

// ---------------- persistent forward recurrence ----------------------------
// 128 CTAs x 256 threads. CTA = (btile 0..3) x (htile 0..31).
// Thread = (kh 0..1, hcol 0..7, bpair 0..15); 2 batches packed via f32x2.
// W_hh in smem once (padded stride 258 f32x2 -> conflict-free); c in registers.
// Sync: per-btile flag words, no atomics, no global counter.
#define WDS      258                      // float2 stride per gate-row / per bpair-row
#define OFF_WD   0
#define OFF_HS   66048                    // 32*258*8
#define OFF_XS   99072                    // + 16*258*8
#define OFF_RED  103680                   // + 32*36*4
#define SMEM_TOT 107776                   // + 128*4*8

__global__ __launch_bounds__(256, 1) void lstm_fwd(const float* __restrict__ Whh)
{
    extern __shared__ char smem[];
    float2* Wd  = reinterpret_cast<float2*>(smem + OFF_WD);
    float2* Hs  = reinterpret_cast<float2*>(smem + OFF_HS);
    float*  Hsf = reinterpret_cast<float*>(Hs);
    float*  Xs  = reinterpret_cast<float*>(smem + OFF_XS);
    ull*    Red = reinterpret_cast<ull*>(smem + OFF_RED);

    int tid = threadIdx.x;
    int kh = tid >> 7;           // k half
    int r  = tid & 127;
    int hcol = r >> 4;           // 0..7
    int bp   = r & 15;           // 0..15
    int cta = blockIdx.x;
    int btile = cta & 3;
    int htile = cta >> 2;
    int b0  = btile * 32 + bp * 2;
    int hcg = htile * 8 + hcol;

    // load W_hh rows for this CTA (8 h-cols x 4 gates), dup'd into f32x2
    for (int idx = tid; idx < 8 * 4 * 256; idx += 256) {
        int hl  = idx >> 10;
        int rem = idx & 1023;
        int gt  = rem >> 8;
        int k   = rem & 255;
        float w = Whh[(size_t)(gt * 256 + htile * 8 + hl) * 256 + k];
        Wd[(hl * 4 + gt) * WDS + k] = make_float2(w, w);
    }

    float c0 = 0.0f, c1 = 0.0f;
    int srow = tid >> 3;                 // 0..31 staging row
    int scol = (tid & 7) * 4;            // 0,4,...,28
    int hs_row = srow >> 1, comp = srow & 1;
    int grow = (srow >> 3) * 256 + htile * 8 + (srow & 7);  // gate row in [0,1024)

    const volatile unsigned* myflags = g_flags + btile * 32;

    for (int t = 0; t < T_; ++t) {
        // A) xp prefetch: 32 coalesced 128B lines per CTA, independent of sync
        float4 xv = *reinterpret_cast<const float4*>(
            g_xp + ((size_t)t * G4_ + grow) * B_ + btile * 32 + scol);

        // B) wait for the 32 producers of this btile to finish step t-1
        if (t > 0 && tid < 32) {
            while (myflags[tid] < (unsigned)t) { }
        }
        __syncthreads();

        // C) stage xp + h into smem
        *reinterpret_cast<float4*>(Xs + srow * 36 + scol) = xv;
        {
            const float* src = g_hst + (t & 1) * (B_ * H_) + (size_t)(btile * 32 + srow) * 256;
#pragma unroll
            for (int i = 0; i < 8; ++i) {
                int k = scol + i * 32;
                float4 v = __ldcg(reinterpret_cast<const float4*>(src + k));
                float* d = Hsf + ((size_t)hs_row * WDS + k) * 2 + comp;
                d[0] = v.x; d[2] = v.y; d[4] = v.z; d[6] = v.w;
            }
        }
        __syncthreads();

        // D) k loop: 128 k per thread, 2 k/iter, f32x2 over batch pair
        ull a_i = 0ull, a_f = 0ull, a_g = 0ull, a_o = 0ull;
        const ulonglong2* hp = reinterpret_cast<const ulonglong2*>(Hs + bp * WDS + kh * 128);
        const ulonglong2* w0 = reinterpret_cast<const ulonglong2*>(Wd + (hcol * 4 + 0) * WDS + kh * 128);
        const ulonglong2* w1 = reinterpret_cast<const ulonglong2*>(Wd + (hcol * 4 + 1) * WDS + kh * 128);
        const ulonglong2* w2 = reinterpret_cast<const ulonglong2*>(Wd + (hcol * 4 + 2) * WDS + kh * 128);
        const ulonglong2* w3 = reinterpret_cast<const ulonglong2*>(Wd + (hcol * 4 + 3) * WDS + kh * 128);
#pragma unroll 16
        for (int it = 0; it < 64; ++it) {
            ulonglong2 hv = hp[it];
            ulonglong2 wa = w0[it]; fma2(a_i, hv.x, wa.x); fma2(a_i, hv.y, wa.y);
            ulonglong2 wb = w1[it]; fma2(a_f, hv.x, wb.x); fma2(a_f, hv.y, wb.y);
            ulonglong2 wc = w2[it]; fma2(a_g, hv.x, wc.x); fma2(a_g, hv.y, wc.y);
            ulonglong2 wd = w3[it]; fma2(a_o, hv.x, wd.x); fma2(a_o, hv.y, wd.y);
        }

        // E) combine k halves
        if (kh == 1) {
            ull* rp = Red + (size_t)r * 4;
            rp[0] = a_i; rp[1] = a_f; rp[2] = a_g; rp[3] = a_o;
        }
        __syncthreads();
        if (kh == 0) {
            ull* rp = Red + (size_t)r * 4;
            float2 si = unpk(a_i), sf = unpk(a_f), sg = unpk(a_g), so = unpk(a_o);
            float2 q;
            q = unpk(rp[0]); si.x += q.x; si.y += q.y;
            q = unpk(rp[1]); sf.x += q.x; sf.y += q.y;
            q = unpk(rp[2]); sg.x += q.x; sg.y += q.y;
            q = unpk(rp[3]); so.x += q.x; so.y += q.y;

            float xi0 = Xs[(0  + hcol) * 36 + 2 * bp], xi1 = Xs[(0  + hcol) * 36 + 2 * bp + 1];
            float xf0 = Xs[(8  + hcol) * 36 + 2 * bp], xf1 = Xs[(8  + hcol) * 36 + 2 * bp + 1];
            float xg0 = Xs[(16 + hcol) * 36 + 2 * bp], xg1 = Xs[(16 + hcol) * 36 + 2 * bp + 1];
            float xo0 = Xs[(24 + hcol) * 36 + 2 * bp], xo1 = Xs[(24 + hcol) * 36 + 2 * bp + 1];

            float* hwrite = g_hst + ((t + 1) & 1) * (B_ * H_);

            float I0 = sigf(si.x + xi0), F0 = sigf(sf.x + xf0);
            float G0 = tanhf(sg.x + xg0), O0 = sigf(so.x + xo0);
            c0 = F0 * c0 + I0 * G0;
            hwrite[(size_t)b0 * 256 + hcg] = O0 * tanhf(c0);

            float I1 = sigf(si.y + xi1), F1 = sigf(sf.y + xf1);
            float G1 = tanhf(sg.y + xg1), O1 = sigf(so.y + xo1);
            c1 = F1 * c1 + I1 * G1;
            hwrite[(size_t)(b0 + 1) * 256 + hcg] = O1 * tanhf(c1);
        }

        // F) publish: writes visible, then set our flag
        __syncthreads();
        if (t < T_ - 1 && tid == 0) {
            __threadfence();
            *((volatile unsigned*)&g_flags[btile * 32 + htile]) = (unsigned)(t + 1);
        }
    }
}

// ---------------- final linear: out = [hf, hb] @ W_lin^T + b_lin -----------
__global__ void final_k(const float* __restrict__ Wl, const float* __restrict__ bl,
                        float* __restrict__ out)
{
    __shared__ float s0[8], s1[8];
    int b = blockIdx.x, h = threadIdx.x;   // 256 threads
    float hf = g_hst[(size_t)b * 256 + h];            // final h in buffer 0
    float hb = g_hb[(size_t)b * 256 + h];
    float p0 = hf * Wl[h]       + hb * Wl[256 + h];
    float p1 = hf * Wl[512 + h] + hb * Wl[768 + h];
#pragma unroll
    for (int o = 16; o; o >>= 1) {
        p0 += __shfl_down_sync(0xffffffffu, p0, o);
        p1 += __shfl_down_sync(0xffffffffu, p1, o);
    }
    if ((h & 31) == 0) { s0[h >> 5] = p0; s1[h >> 5] = p1; }
    __syncthreads();
    if (h == 0) {
        float a = 0.f, c = 0.f;
#pragma unroll
        for (int i = 0; i < 8; ++i) { a += s0[i]; c += s1[i]; }
        out[b * 2 + 0] = a + bl[0];
        out[b * 2 + 1] = c + bl[1];
    }
}

// ---------------- host entry ----------------------------------------------
extern "C" void kernel_launch(void* const* d_in, const int* in_sizes, int n_in,
                              void* d_out, int out_size)
{
    const float* x    = (const float*)d_in[0];
    const float* Wihf = (const float*)d_in[1];
    const float* Whhf = (const float*)d_in[2];
    const float* bf   = (const float*)d_in[3];
    const float* Wihb = (const float*)d_in[4];
    const float* bb   = (const float*)d_in[6];
    const float* Wl   = (const float*)d_in[7];
    const float* bl   = (const float*)d_in[8];
    float* out = (float*)d_out;

    void *xp_p = nullptr, *xpb_p = nullptr;
    cudaGetSymbolAddress(&xp_p, g_xp);
    cudaGetSymbolAddress(&xpb_p, g_xpb);

    static bool attr_set = false;
    if (!attr_set) {
        cudaFuncSetAttribute(lstm_fwd, cudaFuncAttributeMaxDynamicSharedMemorySize, SMEM_TOT);
        attr_set = true;
    }

    // 1) zero h buffer 0 + flags
    init_k<<<128, 256>>>();
    // 2) xp_f = x @ W_ih_f^T + b_f, scattered to [t][g][b]
    sgemm_tn<<<dim3(8, 512), 256>>>(x, I_, Wihf, bf, (float*)xp_p, I_, 1);
    // 3) xp_b at t = T-1 only (row-major [b][g])
    sgemm_tn<<<dim3(8, 1), 256>>>(x + (size_t)(T_ - 1) * I_, T_ * I_, Wihb, bb,
                                  (float*)xpb_p, I_, 0);
    // 4) backward direction = one LSTM step
    bstep_k<<<128, 256>>>();
    // 5) forward recurrence (persistent, 512 steps, flag-based sync)
    lstm_fwd<<<128, 256, SMEM_TOT>>>(Whhf);
    // 6) final linear
    final_k<<<128, 256>>>(Wl, bl, out);
}